// round 12
// baseline (speedup 1.0000x reference)
#include <cuda_runtime.h>
#include <cuda_fp16.h>
#include <cstdint>

#define NMAX   50000
#define EMAX   500000
#define ZDIM   136      // 16 (he) x 8 (x) + 8 (x bias lanes)
#define GRAPHS 64
#define EPS    1e-5f
#define PREP_B 296
#define PREP_T 512

typedef unsigned long long ull;

// packed fp32x2 helpers (Blackwell FFMA2)
#define DUP2(d, s)    asm("mov.b64 %0, {%1, %1};" : "=l"(d) : "f"(s))
#define FMA2(d, a, b) asm("fma.rn.f32x2 %0, %1, %2, %0;" : "+l"(d) : "l"(a), "l"(b))
#define PACK2(d, lo, hi) asm("mov.b64 %0, {%1, %2};" : "=l"(d) : "f"(lo), "f"(hi))
#define UNPACK2(lo, hi, s) asm("mov.b64 {%0, %1}, %2;" : "=f"(lo), "=f"(hi) : "l"(s))

// ---------------- scratch (device globals; zero-initialized at load) ----------------
__device__ int      g_cnt[NMAX];                    // degree histogram (re-zeroed by scan phase)
__device__ int      g_off[NMAX + 1];                // CSR offsets
__device__ int      g_cur[NMAX];                    // scatter cursors
__device__ int      g_bsum[PREP_B];                 // scan block totals+1 (re-zeroed in phase C)
__device__ int      g_ctr[8];                       // grid-barrier counters (cross-reset by kernels)
__device__ int      g_ssrc[EMAX];                   // dst-sorted src ids
__device__ __half2  g_she16[(size_t)EMAX * 8];      // dst-sorted he vectors (fp16, 32 B/edge)
__device__ __half   g_x16[(size_t)NMAX * 8];        // fp16 copy of x (16 B/node)
__device__ float    g_pre[(size_t)NMAX * 64];       // NNConv pre-BN output
__device__ float    g_colsum[64];                   // (re-zeroed in k_post)
__device__ float    g_colsq[64];
__device__ int      g_start[GRAPHS + 1];            // graph boundaries
__device__ float    g_gfeat[GRAPHS * 128];
__device__ float    g_y1[GRAPHS * 256];
__device__ float    g_y2[GRAPHS * 128];

// ---------------- grid-wide barrier (all blocks co-resident) ----------------
__device__ __forceinline__ void grid_barrier(int* ctr, int target) {
    __threadfence();
    __syncthreads();
    if (threadIdx.x == 0) {
        atomicAdd(ctr, 1);
        while (atomicAdd(ctr, 0) < target) { __nanosleep(64); }
    }
    __syncthreads();
}

// edge MLP: ea(8) -> relu(ea@W1+b1) -> fp16x2[8]
__device__ __forceinline__ void edge_mlp(const float* sW1, const float* sB1,
                                         float4 a0, float4 a1, __half2* hp) {
    #pragma unroll
    for (int p = 0; p < 8; p++) {
        float s0 = sB1[2 * p], s1 = sB1[2 * p + 1];
        s0 = fmaf(a0.x, sW1[0 * 16 + 2 * p], s0); s1 = fmaf(a0.x, sW1[0 * 16 + 2 * p + 1], s1);
        s0 = fmaf(a0.y, sW1[1 * 16 + 2 * p], s0); s1 = fmaf(a0.y, sW1[1 * 16 + 2 * p + 1], s1);
        s0 = fmaf(a0.z, sW1[2 * 16 + 2 * p], s0); s1 = fmaf(a0.z, sW1[2 * 16 + 2 * p + 1], s1);
        s0 = fmaf(a0.w, sW1[3 * 16 + 2 * p], s0); s1 = fmaf(a0.w, sW1[3 * 16 + 2 * p + 1], s1);
        s0 = fmaf(a1.x, sW1[4 * 16 + 2 * p], s0); s1 = fmaf(a1.x, sW1[4 * 16 + 2 * p + 1], s1);
        s0 = fmaf(a1.y, sW1[5 * 16 + 2 * p], s0); s1 = fmaf(a1.y, sW1[5 * 16 + 2 * p + 1], s1);
        s0 = fmaf(a1.z, sW1[6 * 16 + 2 * p], s0); s1 = fmaf(a1.z, sW1[6 * 16 + 2 * p + 1], s1);
        s0 = fmaf(a1.w, sW1[7 * 16 + 2 * p], s0); s1 = fmaf(a1.w, sW1[7 * 16 + 2 * p + 1], s1);
        hp[p] = __floats2half2_rn(fmaxf(s0, 0.f), fmaxf(s1, 0.f));
    }
}

// ---------------- launch 1: prep = hist + boundaries + x16 | scan | MLP-scatter ----------------
__global__ void __launch_bounds__(PREP_T, 2)
k_prep(const int* __restrict__ ei,
       const int* __restrict__ batch,
       const float* __restrict__ x,
       const float* __restrict__ ea,
       const float* __restrict__ w_e1,
       const float* __restrict__ b_e1,
       int N, int E) {
    __shared__ float sW1[128];
    __shared__ float sB1[16];
    __shared__ int sv[PREP_T];
    __shared__ int sred[PREP_T];

    int tid = threadIdx.x, b = blockIdx.x;
    int gsz = gridDim.x * blockDim.x;
    int gid = b * blockDim.x + tid;

    if (tid < 128) sW1[tid] = w_e1[tid];
    if (tid < 16)  sB1[tid] = b_e1[tid];
    if (b == 0 && tid < 3) g_ctr[2 + tid] = 0;   // reset k_post's barrier counters
    __syncthreads();

    // ---- phase A: histogram + graph boundaries + x -> fp16 ----
    int cover = (E > N) ? E : N;
    for (int i = gid; i < cover; i += gsz) {
        if (i < E) atomicAdd(&g_cnt[__ldg(&ei[E + i])], 1);
        if (i < N) {
            int bn = __ldg(&batch[i]);
            int bp = (i == 0) ? -1 : __ldg(&batch[i - 1]);
            for (int g = bp + 1; g <= bn; g++) g_start[g] = i;
            if (i == N - 1) {
                for (int g = bn + 1; g <= GRAPHS; g++) g_start[g] = N;
            }
            float4 x0 = __ldg((const float4*)(x + (size_t)i * 8));
            float4 x1 = __ldg((const float4*)(x + (size_t)i * 8 + 4));
            __half2 h[4];
            h[0] = __floats2half2_rn(x0.x, x0.y);
            h[1] = __floats2half2_rn(x0.z, x0.w);
            h[2] = __floats2half2_rn(x1.x, x1.y);
            h[3] = __floats2half2_rn(x1.z, x1.w);
            *(uint4*)(g_x16 + (size_t)i * 8) = *(uint4*)h;
        }
    }
    grid_barrier(&g_ctr[0], PREP_B);

    // ---- phase B: scan (decoupled block totals) ----
    {
        int C = (N + PREP_B - 1) / PREP_B;
        int base0 = b * C, end = min(base0 + C, N);
        int run = 0;
        for (int t0 = base0; t0 < end; t0 += PREP_T) {
            int idx = t0 + tid;
            int v = 0;
            if (idx < end) { v = g_cnt[idx]; g_cnt[idx] = 0; }   // read + reset for next replay
            sv[tid] = v;
            __syncthreads();
            for (int off = 1; off < PREP_T; off <<= 1) {
                int u = (tid >= off) ? sv[tid - off] : 0;
                __syncthreads();
                sv[tid] += u;
                __syncthreads();
            }
            if (idx < end) g_off[idx] = run + sv[tid] - v;       // local exclusive
            run += sv[PREP_T - 1];
            __syncthreads();
        }
        if (tid == 0) atomicExch(&g_bsum[b], run + 1);
        int v = 0;
        if (tid < b) {
            while ((v = atomicAdd(&g_bsum[tid], 0)) == 0) { }
            v -= 1;
        }
        sred[tid] = v;
        __syncthreads();
        for (int off = PREP_T / 2; off > 0; off >>= 1) {
            if (tid < off) sred[tid] += sred[tid + off];
            __syncthreads();
        }
        int base = sred[0];
        for (int idx = base0 + tid; idx < end; idx += PREP_T) {
            int o = g_off[idx] + base;
            g_off[idx] = o;
            g_cur[idx] = o;
        }
        if (b == PREP_B - 1 && tid == 0) g_off[N] = E;
    }
    grid_barrier(&g_ctr[1], PREP_B);

    // ---- phase C: reset g_bsum; MLP + scatter, 2 independent edge streams ----
    if (b == 0) {
        for (int i = tid; i < PREP_B; i += PREP_T) g_bsum[i] = 0;
    }
    for (int e = gid; e < E; e += 2 * gsz) {
        int e2 = e + gsz;
        bool has2 = (e2 < E);

        int srcA = __ldg(&ei[e]);
        int dstA = __ldg(&ei[E + e]);
        float4 a0 = __ldg((const float4*)(ea + (size_t)e * 8));
        float4 a1 = __ldg((const float4*)(ea + (size_t)e * 8 + 4));
        int srcB = 0, dstB = 0;
        float4 c0, c1;
        if (has2) {
            srcB = __ldg(&ei[e2]);
            dstB = __ldg(&ei[E + e2]);
            c0 = __ldg((const float4*)(ea + (size_t)e2 * 8));
            c1 = __ldg((const float4*)(ea + (size_t)e2 * 8 + 4));
        }

        __half2 hpA[8];
        edge_mlp(sW1, sB1, a0, a1, hpA);
        int posA = atomicAdd(&g_cur[dstA], 1);

        if (has2) {
            __half2 hpB[8];
            edge_mlp(sW1, sB1, c0, c1, hpB);
            int posB = atomicAdd(&g_cur[dstB], 1);

            uint4* hrA = (uint4*)(g_she16 + (size_t)posA * 8);
            hrA[0] = *(uint4*)&hpA[0];
            hrA[1] = *(uint4*)&hpA[4];
            g_ssrc[posA] = srcA;
            uint4* hrB = (uint4*)(g_she16 + (size_t)posB * 8);
            hrB[0] = *(uint4*)&hpB[0];
            hrB[1] = *(uint4*)&hpB[4];
            g_ssrc[posB] = srcB;
        } else {
            uint4* hrA = (uint4*)(g_she16 + (size_t)posA * 8);
            hrA[0] = *(uint4*)&hpA[0];
            hrA[1] = *(uint4*)&hpA[4];
            g_ssrc[posA] = srcA;
        }
    }
}

// ---------------- launch 2: fused z-accumulate + node GEMM (f32x2) + BN stats ----------------
// block = 256 threads, 64 nodes, 3 blocks/SM. (unchanged from R10/R11)
__global__ void __launch_bounds__(256, 3)
k_fused(const float* __restrict__ x,
        const float* __restrict__ w_e2,
        const float* __restrict__ b_e2,
        const float* __restrict__ root,
        const float* __restrict__ cbias,
        int N) {
    extern __shared__ char dynsmem[];
    ull*   sWc = (ull*)dynsmem;                          // [136][32] packed col pairs = 34816 B
    float* sZ  = (float*)(dynsmem + ZDIM * 32 * 8);      // [64][136] = 34816 B
    float2* redS = (float2*)sZ;                          // aliased after z reads complete
    float2* redQ = (float2*)(sZ + 512);

    __shared__ float2 sRoot[8][32];
    __shared__ float  sCB[64];
    __shared__ float  sInvDeg[64];

    int tid = threadIdx.x;

    for (int idx = tid; idx < ZDIM * 32; idx += blockDim.x) {
        int k = idx >> 5, l = idx & 31;
        int h0 = 2 * l;
        float a, b;
        if (k < 128) {
            int j = k >> 3, f = k & 7;
            a = w_e2[j * 512 + f * 64 + h0];
            b = w_e2[j * 512 + f * 64 + h0 + 1];
        } else {
            int f = k - 128;
            a = b_e2[f * 64 + h0];
            b = b_e2[f * 64 + h0 + 1];
        }
        ull u; PACK2(u, a, b);
        sWc[k * 32 + l] = u;
    }
    for (int idx = tid; idx < 8 * 32; idx += blockDim.x) {
        int f = idx >> 5, l = idx & 31;
        sRoot[f][l] = make_float2(root[f * 64 + 2 * l], root[f * 64 + 2 * l + 1]);
    }
    if (tid < 64) sCB[tid] = cbias[tid];

    int nFirst = blockIdx.x * 64;

    for (int half = 0; half < 2; half++) {
        int gnode = half * 32 + (tid >> 3);
        int sub   = tid & 7;
        int n = nFirst + gnode;
        int j0 = 2 * sub;
        int o0 = 0, o1 = 0;
        if (n < N) {
            o0 = __ldg(&g_off[n]);
            o1 = __ldg(&g_off[n + 1]);
        }

        float zacc[16];
        #pragma unroll
        for (int i = 0; i < 16; i++) zacc[i] = 0.f;
        float xs[8];
        #pragma unroll
        for (int i = 0; i < 8; i++) xs[i] = 0.f;

        int i = o0;
        int sA = 0, sB = 0;
        __half2 hA2, hB2;
        if (i + 2 <= o1) {
            sA  = __ldg(&g_ssrc[i]);
            sB  = __ldg(&g_ssrc[i + 1]);
            hA2 = __ldg(g_she16 + (size_t)i * 8 + sub);
            hB2 = __ldg(g_she16 + (size_t)(i + 1) * 8 + sub);
        }
        for (; i + 2 <= o1; i += 2) {
            uint4 xAu = __ldg((const uint4*)(g_x16 + (size_t)sA * 8));
            uint4 xBu = __ldg((const uint4*)(g_x16 + (size_t)sB * 8));
            float2 hA = __half22float2(hA2);
            float2 hB = __half22float2(hB2);

            int ip = (i + 4 <= o1) ? i + 2 : i;
            sA  = __ldg(&g_ssrc[ip]);
            sB  = __ldg(&g_ssrc[ip + 1]);
            hA2 = __ldg(g_she16 + (size_t)ip * 8 + sub);
            hB2 = __ldg(g_she16 + (size_t)(ip + 1) * 8 + sub);

            __half2* phA = (__half2*)&xAu;
            __half2* phB = (__half2*)&xBu;
            float2 a0 = __half22float2(phA[0]);
            float2 a1 = __half22float2(phA[1]);
            float2 a2 = __half22float2(phA[2]);
            float2 a3 = __half22float2(phA[3]);
            float2 b0 = __half22float2(phB[0]);
            float2 b1 = __half22float2(phB[1]);
            float2 b2 = __half22float2(phB[2]);
            float2 b3 = __half22float2(phB[3]);

            zacc[0] = fmaf(hA.x, a0.x, zacc[0]);
            zacc[1] = fmaf(hA.x, a0.y, zacc[1]);
            zacc[2] = fmaf(hA.x, a1.x, zacc[2]);
            zacc[3] = fmaf(hA.x, a1.y, zacc[3]);
            zacc[4] = fmaf(hA.x, a2.x, zacc[4]);
            zacc[5] = fmaf(hA.x, a2.y, zacc[5]);
            zacc[6] = fmaf(hA.x, a3.x, zacc[6]);
            zacc[7] = fmaf(hA.x, a3.y, zacc[7]);
            zacc[8]  = fmaf(hA.y, a0.x, zacc[8]);
            zacc[9]  = fmaf(hA.y, a0.y, zacc[9]);
            zacc[10] = fmaf(hA.y, a1.x, zacc[10]);
            zacc[11] = fmaf(hA.y, a1.y, zacc[11]);
            zacc[12] = fmaf(hA.y, a2.x, zacc[12]);
            zacc[13] = fmaf(hA.y, a2.y, zacc[13]);
            zacc[14] = fmaf(hA.y, a3.x, zacc[14]);
            zacc[15] = fmaf(hA.y, a3.y, zacc[15]);

            zacc[0] = fmaf(hB.x, b0.x, zacc[0]);
            zacc[1] = fmaf(hB.x, b0.y, zacc[1]);
            zacc[2] = fmaf(hB.x, b1.x, zacc[2]);
            zacc[3] = fmaf(hB.x, b1.y, zacc[3]);
            zacc[4] = fmaf(hB.x, b2.x, zacc[4]);
            zacc[5] = fmaf(hB.x, b2.y, zacc[5]);
            zacc[6] = fmaf(hB.x, b3.x, zacc[6]);
            zacc[7] = fmaf(hB.x, b3.y, zacc[7]);
            zacc[8]  = fmaf(hB.y, b0.x, zacc[8]);
            zacc[9]  = fmaf(hB.y, b0.y, zacc[9]);
            zacc[10] = fmaf(hB.y, b1.x, zacc[10]);
            zacc[11] = fmaf(hB.y, b1.y, zacc[11]);
            zacc[12] = fmaf(hB.y, b2.x, zacc[12]);
            zacc[13] = fmaf(hB.y, b2.y, zacc[13]);
            zacc[14] = fmaf(hB.y, b3.x, zacc[14]);
            zacc[15] = fmaf(hB.y, b3.y, zacc[15]);

            if (sub == 0) {
                xs[0] += a0.x + b0.x; xs[1] += a0.y + b0.y;
                xs[2] += a1.x + b1.x; xs[3] += a1.y + b1.y;
                xs[4] += a2.x + b2.x; xs[5] += a2.y + b2.y;
                xs[6] += a3.x + b3.x; xs[7] += a3.y + b3.y;
            }
        }
        if (i < o1) {
            int src = __ldg(&g_ssrc[i]);
            __half2 hh = __ldg(g_she16 + (size_t)i * 8 + sub);
            uint4 xu = __ldg((const uint4*)(g_x16 + (size_t)src * 8));
            float2 h2 = __half22float2(hh);
            __half2* ph = (__half2*)&xu;
            float2 a0 = __half22float2(ph[0]);
            float2 a1 = __half22float2(ph[1]);
            float2 a2 = __half22float2(ph[2]);
            float2 a3 = __half22float2(ph[3]);
            zacc[0] = fmaf(h2.x, a0.x, zacc[0]);
            zacc[1] = fmaf(h2.x, a0.y, zacc[1]);
            zacc[2] = fmaf(h2.x, a1.x, zacc[2]);
            zacc[3] = fmaf(h2.x, a1.y, zacc[3]);
            zacc[4] = fmaf(h2.x, a2.x, zacc[4]);
            zacc[5] = fmaf(h2.x, a2.y, zacc[5]);
            zacc[6] = fmaf(h2.x, a3.x, zacc[6]);
            zacc[7] = fmaf(h2.x, a3.y, zacc[7]);
            zacc[8]  = fmaf(h2.y, a0.x, zacc[8]);
            zacc[9]  = fmaf(h2.y, a0.y, zacc[9]);
            zacc[10] = fmaf(h2.y, a1.x, zacc[10]);
            zacc[11] = fmaf(h2.y, a1.y, zacc[11]);
            zacc[12] = fmaf(h2.y, a2.x, zacc[12]);
            zacc[13] = fmaf(h2.y, a2.y, zacc[13]);
            zacc[14] = fmaf(h2.y, a3.x, zacc[14]);
            zacc[15] = fmaf(h2.y, a3.y, zacc[15]);
            if (sub == 0) {
                xs[0] += a0.x; xs[1] += a0.y; xs[2] += a1.x; xs[3] += a1.y;
                xs[4] += a2.x; xs[5] += a2.y; xs[6] += a3.x; xs[7] += a3.y;
            }
        }

        float* zrow = sZ + gnode * ZDIM;
        #pragma unroll
        for (int f = 0; f < 8; f++) {
            zrow[j0 * 8 + f]       = zacc[f];
            zrow[(j0 + 1) * 8 + f] = zacc[8 + f];
        }
        if (sub == 0) {
            #pragma unroll
            for (int f = 0; f < 8; f++) zrow[128 + f] = xs[f];
            sInvDeg[gnode] = 1.f / fmaxf((float)(o1 - o0), 1.f);
        }
    }
    __syncthreads();

    int warp = tid >> 5, lane = tid & 31;
    int nlocbase = warp * 8;
    int nbase = nFirst + nlocbase;

    int  nn[8];
    bool valid[8];
    #pragma unroll
    for (int i = 0; i < 8; i++) {
        int nd = nbase + i;
        valid[i] = (nd < N);
        nn[i] = valid[i] ? nd : 0;
    }

    const float4* zr[8];
    #pragma unroll
    for (int i = 0; i < 8; i++)
        zr[i] = (const float4*)(sZ + (size_t)(nlocbase + i) * ZDIM);

    ull agg[8];
    #pragma unroll
    for (int i = 0; i < 8; i++) agg[i] = 0ull;

    for (int kk = 0; kk < ZDIM / 4; kk++) {
        ull wa = sWc[(4 * kk + 0) * 32 + lane];
        ull wb = sWc[(4 * kk + 1) * 32 + lane];
        ull wc = sWc[(4 * kk + 2) * 32 + lane];
        ull wd = sWc[(4 * kk + 3) * 32 + lane];
        #pragma unroll
        for (int i = 0; i < 8; i++) {
            float4 z = zr[i][kk];
            ull t;
            DUP2(t, z.x); FMA2(agg[i], t, wa);
            DUP2(t, z.y); FMA2(agg[i], t, wb);
            DUP2(t, z.z); FMA2(agg[i], t, wc);
            DUP2(t, z.w); FMA2(agg[i], t, wd);
        }
    }

    float2 ls = make_float2(0.f, 0.f), lq = make_float2(0.f, 0.f);
    #pragma unroll
    for (int i = 0; i < 8; i++) {
        float ax, ay;
        UNPACK2(ax, ay, agg[i]);
        float2 p = make_float2(sCB[2 * lane], sCB[2 * lane + 1]);
        const float* xr = x + (size_t)nn[i] * 8;
        #pragma unroll
        for (int f = 0; f < 8; f++) {
            float xv = __ldg(xr + f);
            float2 rw = sRoot[f][lane];
            p.x = fmaf(xv, rw.x, p.x);
            p.y = fmaf(xv, rw.y, p.y);
        }
        float invd = sInvDeg[nlocbase + i];
        p.x = fmaf(ax, invd, p.x);
        p.y = fmaf(ay, invd, p.y);
        if (valid[i]) {
            g_pre[(size_t)nn[i] * 64 + 2 * lane]     = p.x;
            g_pre[(size_t)nn[i] * 64 + 2 * lane + 1] = p.y;
            ls.x += p.x; ls.y += p.y;
            lq.x = fmaf(p.x, p.x, lq.x);
            lq.y = fmaf(p.y, p.y, lq.y);
        }
    }
    __syncthreads();
    redS[warp * 32 + lane] = ls;
    redQ[warp * 32 + lane] = lq;
    __syncthreads();
    if (tid < 32) {
        float2 S = make_float2(0.f, 0.f), Q = make_float2(0.f, 0.f);
        #pragma unroll
        for (int w = 0; w < 8; w++) {
            S.x += redS[w * 32 + tid].x; S.y += redS[w * 32 + tid].y;
            Q.x += redQ[w * 32 + tid].x; Q.y += redQ[w * 32 + tid].y;
        }
        atomicAdd(&g_colsum[2 * tid],     S.x);
        atomicAdd(&g_colsum[2 * tid + 1], S.y);
        atomicAdd(&g_colsq[2 * tid],      Q.x);
        atomicAdd(&g_colsq[2 * tid + 1],  Q.y);
    }
}

// ---------------- layer phase helper for k_post (1024-thread blocks) ----------------
__device__ __forceinline__ void layer_phase(
    float* sIn, float* redS, float* redQ, float* sScale, float* sShift,
    const float* __restrict__ in, const float* __restrict__ w,
    const float* __restrict__ b, const float* __restrict__ gam,
    const float* __restrict__ bet, float* __restrict__ out,
    int I, int O, int nBlk)
{
    int tid = threadIdx.x;
    bool act = ((int)blockIdx.x < nBlk);
    if (act) {
        for (int idx = tid; idx < 64 * I; idx += 1024) sIn[idx] = in[idx];
    }
    __syncthreads();

    int c = tid & 31, r0 = (tid >> 5) & 7;
    int cg = blockIdx.x * 32 + c;
    bool work = act && (tid < 256);

    float acc[8];
    if (work) {
        float bv = __ldg(&b[cg]);
        #pragma unroll
        for (int i = 0; i < 8; i++) acc[i] = bv;
        for (int k = 0; k < I; k++) {
            float wv = __ldg(&w[k * O + cg]);
            #pragma unroll
            for (int i = 0; i < 8; i++)
                acc[i] = fmaf(sIn[(r0 + 8 * i) * I + k], wv, acc[i]);
        }
        float s = 0.f, q = 0.f;
        #pragma unroll
        for (int i = 0; i < 8; i++) { s += acc[i]; q = fmaf(acc[i], acc[i], q); }
        redS[r0 * 32 + c] = s;
        redQ[r0 * 32 + c] = q;
    }
    __syncthreads();
    if (act && tid < 32) {
        float S = 0.f, Q = 0.f;
        #pragma unroll
        for (int w8 = 0; w8 < 8; w8++) { S += redS[w8 * 32 + tid]; Q += redQ[w8 * 32 + tid]; }
        float m = S * (1.f / 64.f);
        float v = Q * (1.f / 64.f) - m * m;
        float r = rsqrtf(v + EPS);
        float sc = r * __ldg(&gam[blockIdx.x * 32 + tid]);
        sScale[tid] = sc;
        sShift[tid] = __ldg(&bet[blockIdx.x * 32 + tid]) - m * sc;
    }
    __syncthreads();
    if (work) {
        float sc = sScale[c], sh = sShift[c];
        #pragma unroll
        for (int i = 0; i < 8; i++)
            out[(r0 + 8 * i) * O + cg] = fmaxf(fmaf(acc[i], sc, sh), 0.f);
    }
    __syncthreads();
}

// ---------------- launch 3: post = pool | layer1 | layer2 | layer3+out ----------------
__global__ void __launch_bounds__(1024, 1)
k_post(const float* __restrict__ g_bnc, const float* __restrict__ b_bnc,
       const float* __restrict__ w1, const float* __restrict__ b1,
       const float* __restrict__ g1, const float* __restrict__ be1,
       const float* __restrict__ w2, const float* __restrict__ b2,
       const float* __restrict__ g2, const float* __restrict__ be2,
       const float* __restrict__ w3, const float* __restrict__ b3,
       const float* __restrict__ g3, const float* __restrict__ be3,
       const float* __restrict__ wout, const float* __restrict__ bout,
       float* __restrict__ out, int N) {
    extern __shared__ float sm[];                      // 64KB dynamic: layer sIn / sY
    __shared__ float redA[16][64];                     // pool sums / layer3 redS
    __shared__ float redB[16][64];                     // pool maxes / layer3 redQ
    __shared__ float sScale[64], sShift[64];
    __shared__ float redS[8 * 32], redQ[8 * 32];       // layer1/2 reductions

    int tid = threadIdx.x, b = blockIdx.x;
    if (b == 0 && tid < 2) g_ctr[tid] = 0;             // reset k_prep's barrier counters

    // ---- pool (per-graph, 64 blocks), unroll 2 ----
    if (tid < 64) {
        float invN = 1.f / (float)N;
        float m = g_colsum[tid] * invN;
        float v = g_colsq[tid] * invN - m * m;
        float r = rsqrtf(v + EPS);
        float sc = r * __ldg(&g_bnc[tid]);
        sScale[tid] = sc;
        sShift[tid] = __ldg(&b_bnc[tid]) - m * sc;
    }
    __syncthreads();
    {
        int rg = tid >> 6;       // 0..15
        int c  = tid & 63;
        int s0 = g_start[b], s1 = g_start[b + 1];
        float sc = sScale[c], sh = sShift[c];
        float sum = 0.f, mx = 0.f;
        int n = s0 + rg;
        for (; n + 16 < s1; n += 32) {
            float p1 = __ldg(&g_pre[(size_t)n * 64 + c]);
            float p2 = __ldg(&g_pre[(size_t)(n + 16) * 64 + c]);
            float h1 = fmaxf(fmaf(p1, sc, sh), 0.f);
            float h2 = fmaxf(fmaf(p2, sc, sh), 0.f);
            sum += h1 + h2;
            mx = fmaxf(mx, fmaxf(h1, h2));
        }
        if (n < s1) {
            float p1 = __ldg(&g_pre[(size_t)n * 64 + c]);
            float h1 = fmaxf(fmaf(p1, sc, sh), 0.f);
            sum += h1;
            mx = fmaxf(mx, h1);
        }
        redA[rg][c] = sum;
        redB[rg][c] = mx;
        __syncthreads();
        if (tid < 64) {
            float S = 0.f, M = 0.f;
            #pragma unroll
            for (int r = 0; r < 16; r++) { S += redA[r][tid]; M = fmaxf(M, redB[r][tid]); }
            int cnt = s1 - s0;
            g_gfeat[b * 128 + tid]      = S / fmaxf((float)cnt, 1.f);
            g_gfeat[b * 128 + 64 + tid] = (cnt > 0) ? M : 0.f;
            g_colsum[tid] = 0.f;       // reset for next replay
            g_colsq[tid]  = 0.f;
        }
    }
    grid_barrier(&g_ctr[2], GRAPHS);

    // ---- layer1: 8 blocks, I=128 O=256 ----
    layer_phase(sm, redS, redQ, sScale, sShift, g_gfeat, w1, b1, g1, be1, g_y1, 128, 256, 8);
    grid_barrier(&g_ctr[3], GRAPHS);

    // ---- layer2: 4 blocks, I=256 O=128 ----
    layer_phase(sm, redS, redQ, sScale, sShift, g_y1, w2, b2, g2, be2, g_y2, 256, 128, 4);
    grid_barrier(&g_ctr[4], GRAPHS);

    // ---- layer3 + final projection (block 0) ----
    if (b == 0) {
        float* sIn = sm;              // 64*128 floats
        float* sY  = sm + 64 * 128;   // 64*64 floats
        for (int idx = tid; idx < 64 * 128; idx += 1024) sIn[idx] = g_y2[idx];
        __syncthreads();

        int c = tid & 63, r0 = (tid >> 6) & 7;
        bool work = (tid < 512);
        float acc[8];
        if (work) {
            float bv = __ldg(&b3[c]);
            #pragma unroll
            for (int i = 0; i < 8; i++) acc[i] = bv;
            for (int k = 0; k < 128; k++) {
                float wv = __ldg(&w3[k * 64 + c]);
                #pragma unroll
                for (int i = 0; i < 8; i++)
                    acc[i] = fmaf(sIn[(r0 + 8 * i) * 128 + k], wv, acc[i]);
            }
            float s = 0.f, q = 0.f;
            #pragma unroll
            for (int i = 0; i < 8; i++) { s += acc[i]; q = fmaf(acc[i], acc[i], q); }
            redA[r0][c] = s;
            redB[r0][c] = q;
        }
        __syncthreads();
        if (tid < 64) {
            float S = 0.f, Q = 0.f;
            #pragma unroll
            for (int r = 0; r < 8; r++) { S += redA[r][tid]; Q += redB[r][tid]; }
            float m = S * (1.f / 64.f);
            float v = Q * (1.f / 64.f) - m * m;
            float r2 = rsqrtf(v + EPS);
            float sc = r2 * __ldg(&g3[tid]);
            sScale[tid] = sc;
            sShift[tid] = __ldg(&be3[tid]) - m * sc;
        }
        __syncthreads();
        if (work) {
            float sc = sScale[c], sh = sShift[c];
            #pragma unroll
            for (int i = 0; i < 8; i++)
                sY[(r0 + 8 * i) * 64 + c] = fmaxf(fmaf(acc[i], sc, sh), 0.f);
        }
        __syncthreads();
        for (int t = tid; t < GRAPHS * 10; t += 1024) {
            int g = t / 10, o = t % 10;
            float s2 = __ldg(&bout[o]);
            #pragma unroll
            for (int k = 0; k < 64; k++)
                s2 = fmaf(sY[g * 64 + k], __ldg(&wout[k * 10 + o]), s2);
            out[t] = s2;
        }
    }
}

// ---------------- launch ----------------
extern "C" void kernel_launch(void* const* d_in, const int* in_sizes, int n_in,
                              void* d_out, int out_size) {
    const float* x      = (const float*)d_in[0];
    const int*   ei     = (const int*)  d_in[1];
    const float* ea     = (const float*)d_in[2];
    const int*   batch  = (const int*)  d_in[3];
    const float* w_e1   = (const float*)d_in[4];
    const float* b_e1   = (const float*)d_in[5];
    const float* w_e2   = (const float*)d_in[6];
    const float* b_e2   = (const float*)d_in[7];
    const float* root   = (const float*)d_in[8];
    const float* cbias  = (const float*)d_in[9];
    const float* g_bnc  = (const float*)d_in[10];
    const float* b_bnc  = (const float*)d_in[11];
    const float* w1     = (const float*)d_in[12];
    const float* b1     = (const float*)d_in[13];
    const float* g1     = (const float*)d_in[14];
    const float* be1    = (const float*)d_in[15];
    const float* w2     = (const float*)d_in[16];
    const float* b2     = (const float*)d_in[17];
    const float* g2     = (const float*)d_in[18];
    const float* be2    = (const float*)d_in[19];
    const float* w3     = (const float*)d_in[20];
    const float* b3     = (const float*)d_in[21];
    const float* g3     = (const float*)d_in[22];
    const float* be3    = (const float*)d_in[23];
    const float* wout   = (const float*)d_in[24];
    const float* bout   = (const float*)d_in[25];

    int N = in_sizes[0] / 8;
    int E = in_sizes[2] / 8;
    if (N > NMAX) N = NMAX;
    if (E > EMAX) E = EMAX;

    const int fusedSmem = ZDIM * 32 * 8 + 64 * ZDIM * 4;     // 69632 B
    const int postSmem  = 64 * 256 * (int)sizeof(float);     // 65536 B
    cudaFuncSetAttribute(k_fused, cudaFuncAttributeMaxDynamicSharedMemorySize, fusedSmem);
    cudaFuncSetAttribute(k_post,  cudaFuncAttributeMaxDynamicSharedMemorySize, postSmem);

    k_prep<<<PREP_B, PREP_T>>>(ei, batch, x, ea, w_e1, b_e1, N, E);
    k_fused<<<(N + 63) / 64, 256, fusedSmem>>>(x, w_e2, b_e2, root, cbias, N);
    k_post<<<GRAPHS, 1024, postSmem>>>(g_bnc, b_bnc, w1, b1, g1, be1,
                                       w2, b2, g2, be2, w3, b3, g3, be3,
                                       wout, bout, (float*)d_out, N);
}

// round 13
// speedup vs baseline: 1.6698x; 1.6698x over previous
#include <cuda_runtime.h>
#include <cuda_fp16.h>
#include <cstdint>

#define NMAX   50000
#define EMAX   500000
#define ZDIM   136      // 16 (he) x 8 (x) + 8 (x bias lanes)
#define GRAPHS 64
#define EPS    1e-5f
#define PREP_B 256
#define PREP_T 512

typedef unsigned long long ull;

// packed fp32x2 helpers (Blackwell FFMA2)
#define DUP2(d, s)    asm("mov.b64 %0, {%1, %1};" : "=l"(d) : "f"(s))
#define FMA2(d, a, b) asm("fma.rn.f32x2 %0, %1, %2, %0;" : "+l"(d) : "l"(a), "l"(b))
#define PACK2(d, lo, hi) asm("mov.b64 %0, {%1, %2};" : "=l"(d) : "f"(lo), "f"(hi))
#define UNPACK2(lo, hi, s) asm("mov.b64 {%0, %1}, %2;" : "=f"(lo), "=f"(hi) : "l"(s))

// ---------------- scratch (device globals; zero-initialized at load) ----------------
__device__ int      g_cnt[NMAX];                    // degree histogram (re-zeroed by scan phase)
__device__ int      g_off[NMAX + 1];                // CSR offsets
__device__ int      g_cur[NMAX];                    // scatter cursors
__device__ int      g_bsum[PREP_B];                 // scan block totals+1 (re-zeroed in phase C)
__device__ int      g_ctr[8];                       // grid-barrier counters (cross-reset by kernels)
__device__ int      g_ssrc[EMAX];                   // dst-sorted src ids
__device__ __half2  g_she16[(size_t)EMAX * 8];      // dst-sorted he vectors (fp16, 32 B/edge)
__device__ __half   g_x16[(size_t)NMAX * 8];        // fp16 copy of x (16 B/node)
__device__ float    g_pre[(size_t)NMAX * 64];       // NNConv pre-BN output
__device__ float    g_colsum[64];                   // (re-zeroed in k_post)
__device__ float    g_colsq[64];
__device__ int      g_start[GRAPHS + 1];            // graph boundaries
__device__ float    g_gfeat[GRAPHS * 128];
__device__ float    g_y1[GRAPHS * 256];
__device__ float    g_y2[GRAPHS * 128];

// ---------------- grid-wide barrier (all blocks co-resident) ----------------
__device__ __forceinline__ void grid_barrier(int* ctr, int target) {
    __threadfence();
    __syncthreads();
    if (threadIdx.x == 0) {
        atomicAdd(ctr, 1);
        while (atomicAdd(ctr, 0) < target) { __nanosleep(64); }
    }
    __syncthreads();
}

// ---------------- launch 1: prep = hist + boundaries + x16 | scan | MLP-scatter ----------------
__global__ void __launch_bounds__(PREP_T, 2)
k_prep(const int* __restrict__ ei,
       const int* __restrict__ batch,
       const float* __restrict__ x,
       const float* __restrict__ ea,
       const float* __restrict__ w_e1,
       const float* __restrict__ b_e1,
       int N, int E) {
    __shared__ float sW1[128];
    __shared__ float sB1[16];
    __shared__ int sv[PREP_T];
    __shared__ int sred[PREP_T];

    int tid = threadIdx.x, b = blockIdx.x;
    int gsz = gridDim.x * blockDim.x;
    int gid = b * blockDim.x + tid;

    if (tid < 128) sW1[tid] = w_e1[tid];
    if (tid < 16)  sB1[tid] = b_e1[tid];
    if (b == 0 && tid < 3) g_ctr[2 + tid] = 0;   // reset k_post's barrier counters
    __syncthreads();

    // ---- phase A: histogram + graph boundaries + x -> fp16 ----
    int cover = (E > N) ? E : N;
    for (int i = gid; i < cover; i += gsz) {
        if (i < E) atomicAdd(&g_cnt[__ldg(&ei[E + i])], 1);
        if (i < N) {
            int bn = __ldg(&batch[i]);
            int bp = (i == 0) ? -1 : __ldg(&batch[i - 1]);
            for (int g = bp + 1; g <= bn; g++) g_start[g] = i;
            if (i == N - 1) {
                for (int g = bn + 1; g <= GRAPHS; g++) g_start[g] = N;
            }
            float4 x0 = __ldg((const float4*)(x + (size_t)i * 8));
            float4 x1 = __ldg((const float4*)(x + (size_t)i * 8 + 4));
            __half2 h[4];
            h[0] = __floats2half2_rn(x0.x, x0.y);
            h[1] = __floats2half2_rn(x0.z, x0.w);
            h[2] = __floats2half2_rn(x1.x, x1.y);
            h[3] = __floats2half2_rn(x1.z, x1.w);
            *(uint4*)(g_x16 + (size_t)i * 8) = *(uint4*)h;
        }
    }
    grid_barrier(&g_ctr[0], PREP_B);

    // ---- phase B: scan (decoupled block totals) ----
    {
        int C = (N + PREP_B - 1) / PREP_B;
        int base0 = b * C, end = min(base0 + C, N);
        int run = 0;
        for (int t0 = base0; t0 < end; t0 += PREP_T) {
            int idx = t0 + tid;
            int v = 0;
            if (idx < end) { v = g_cnt[idx]; g_cnt[idx] = 0; }   // read + reset for next replay
            sv[tid] = v;
            __syncthreads();
            for (int off = 1; off < PREP_T; off <<= 1) {
                int u = (tid >= off) ? sv[tid - off] : 0;
                __syncthreads();
                sv[tid] += u;
                __syncthreads();
            }
            if (idx < end) g_off[idx] = run + sv[tid] - v;       // local exclusive
            run += sv[PREP_T - 1];
            __syncthreads();
        }
        if (tid == 0) atomicExch(&g_bsum[b], run + 1);
        int v = 0;
        if (tid < b) {
            while ((v = atomicAdd(&g_bsum[tid], 0)) == 0) { }
            v -= 1;
        }
        sred[tid] = v;
        __syncthreads();
        for (int off = PREP_T / 2; off > 0; off >>= 1) {
            if (tid < off) sred[tid] += sred[tid + off];
            __syncthreads();
        }
        int base = sred[0];
        for (int idx = base0 + tid; idx < end; idx += PREP_T) {
            int o = g_off[idx] + base;
            g_off[idx] = o;
            g_cur[idx] = o;
        }
        if (b == PREP_B - 1 && tid == 0) g_off[N] = E;
    }
    grid_barrier(&g_ctr[1], PREP_B);

    // ---- phase C: reset g_bsum; MLP + scatter (he fp16 at sorted pos) ----
    if (b == 0) {
        for (int i = tid; i < PREP_B; i += PREP_T) g_bsum[i] = 0;
    }
    for (int e = gid; e < E; e += gsz) {
        int src = __ldg(&ei[e]);
        int dst = __ldg(&ei[E + e]);
        float4 a0 = __ldg((const float4*)(ea + (size_t)e * 8));
        float4 a1 = __ldg((const float4*)(ea + (size_t)e * 8 + 4));

        __half2 hp[8];
        #pragma unroll
        for (int p = 0; p < 8; p++) {
            float s0 = sB1[2 * p], s1 = sB1[2 * p + 1];
            s0 = fmaf(a0.x, sW1[0 * 16 + 2 * p], s0); s1 = fmaf(a0.x, sW1[0 * 16 + 2 * p + 1], s1);
            s0 = fmaf(a0.y, sW1[1 * 16 + 2 * p], s0); s1 = fmaf(a0.y, sW1[1 * 16 + 2 * p + 1], s1);
            s0 = fmaf(a0.z, sW1[2 * 16 + 2 * p], s0); s1 = fmaf(a0.z, sW1[2 * 16 + 2 * p + 1], s1);
            s0 = fmaf(a0.w, sW1[3 * 16 + 2 * p], s0); s1 = fmaf(a0.w, sW1[3 * 16 + 2 * p + 1], s1);
            s0 = fmaf(a1.x, sW1[4 * 16 + 2 * p], s0); s1 = fmaf(a1.x, sW1[4 * 16 + 2 * p + 1], s1);
            s0 = fmaf(a1.y, sW1[5 * 16 + 2 * p], s0); s1 = fmaf(a1.y, sW1[5 * 16 + 2 * p + 1], s1);
            s0 = fmaf(a1.z, sW1[6 * 16 + 2 * p], s0); s1 = fmaf(a1.z, sW1[6 * 16 + 2 * p + 1], s1);
            s0 = fmaf(a1.w, sW1[7 * 16 + 2 * p], s0); s1 = fmaf(a1.w, sW1[7 * 16 + 2 * p + 1], s1);
            hp[p] = __floats2half2_rn(fmaxf(s0, 0.f), fmaxf(s1, 0.f));
        }

        int pos = atomicAdd(&g_cur[dst], 1);
        uint4* hr = (uint4*)(g_she16 + (size_t)pos * 8);
        hr[0] = *(uint4*)&hp[0];
        hr[1] = *(uint4*)&hp[4];
        g_ssrc[pos] = src;
    }
}

// ---------------- launch 2: fused z-accumulate + node GEMM (f32x2) + BN stats ----------------
// block = 256 threads, 64 nodes, 3 blocks/SM.
__global__ void __launch_bounds__(256, 3)
k_fused(const float* __restrict__ x,
        const float* __restrict__ w_e2,
        const float* __restrict__ b_e2,
        const float* __restrict__ root,
        const float* __restrict__ cbias,
        int N) {
    extern __shared__ char dynsmem[];
    ull*   sWc = (ull*)dynsmem;                          // [136][32] packed col pairs = 34816 B
    float* sZ  = (float*)(dynsmem + ZDIM * 32 * 8);      // [64][136] = 34816 B
    float2* redS = (float2*)sZ;                          // aliased after z reads complete
    float2* redQ = (float2*)(sZ + 512);

    __shared__ float2 sRoot[8][32];
    __shared__ float  sCB[64];
    __shared__ float  sInvDeg[64];

    int tid = threadIdx.x;

    for (int idx = tid; idx < ZDIM * 32; idx += blockDim.x) {
        int k = idx >> 5, l = idx & 31;
        int h0 = 2 * l;
        float a, b;
        if (k < 128) {
            int j = k >> 3, f = k & 7;
            a = w_e2[j * 512 + f * 64 + h0];
            b = w_e2[j * 512 + f * 64 + h0 + 1];
        } else {
            int f = k - 128;
            a = b_e2[f * 64 + h0];
            b = b_e2[f * 64 + h0 + 1];
        }
        ull u; PACK2(u, a, b);
        sWc[k * 32 + l] = u;
    }
    for (int idx = tid; idx < 8 * 32; idx += blockDim.x) {
        int f = idx >> 5, l = idx & 31;
        sRoot[f][l] = make_float2(root[f * 64 + 2 * l], root[f * 64 + 2 * l + 1]);
    }
    if (tid < 64) sCB[tid] = cbias[tid];

    int nFirst = blockIdx.x * 64;

    for (int half = 0; half < 2; half++) {
        int gnode = half * 32 + (tid >> 3);
        int sub   = tid & 7;
        int n = nFirst + gnode;
        int j0 = 2 * sub;
        int o0 = 0, o1 = 0;
        if (n < N) {
            o0 = __ldg(&g_off[n]);
            o1 = __ldg(&g_off[n + 1]);
        }

        float zacc[16];
        #pragma unroll
        for (int i = 0; i < 16; i++) zacc[i] = 0.f;
        float xs[8];
        #pragma unroll
        for (int i = 0; i < 8; i++) xs[i] = 0.f;

        int i = o0;
        int sA = 0, sB = 0;
        __half2 hA2, hB2;
        if (i + 2 <= o1) {
            sA  = __ldg(&g_ssrc[i]);
            sB  = __ldg(&g_ssrc[i + 1]);
            hA2 = __ldg(g_she16 + (size_t)i * 8 + sub);
            hB2 = __ldg(g_she16 + (size_t)(i + 1) * 8 + sub);
        }
        for (; i + 2 <= o1; i += 2) {
            uint4 xAu = __ldg((const uint4*)(g_x16 + (size_t)sA * 8));
            uint4 xBu = __ldg((const uint4*)(g_x16 + (size_t)sB * 8));
            float2 hA = __half22float2(hA2);
            float2 hB = __half22float2(hB2);

            int ip = (i + 4 <= o1) ? i + 2 : i;
            sA  = __ldg(&g_ssrc[ip]);
            sB  = __ldg(&g_ssrc[ip + 1]);
            hA2 = __ldg(g_she16 + (size_t)ip * 8 + sub);
            hB2 = __ldg(g_she16 + (size_t)(ip + 1) * 8 + sub);

            __half2* phA = (__half2*)&xAu;
            __half2* phB = (__half2*)&xBu;
            float2 a0 = __half22float2(phA[0]);
            float2 a1 = __half22float2(phA[1]);
            float2 a2 = __half22float2(phA[2]);
            float2 a3 = __half22float2(phA[3]);
            float2 b0 = __half22float2(phB[0]);
            float2 b1 = __half22float2(phB[1]);
            float2 b2 = __half22float2(phB[2]);
            float2 b3 = __half22float2(phB[3]);

            zacc[0] = fmaf(hA.x, a0.x, zacc[0]);
            zacc[1] = fmaf(hA.x, a0.y, zacc[1]);
            zacc[2] = fmaf(hA.x, a1.x, zacc[2]);
            zacc[3] = fmaf(hA.x, a1.y, zacc[3]);
            zacc[4] = fmaf(hA.x, a2.x, zacc[4]);
            zacc[5] = fmaf(hA.x, a2.y, zacc[5]);
            zacc[6] = fmaf(hA.x, a3.x, zacc[6]);
            zacc[7] = fmaf(hA.x, a3.y, zacc[7]);
            zacc[8]  = fmaf(hA.y, a0.x, zacc[8]);
            zacc[9]  = fmaf(hA.y, a0.y, zacc[9]);
            zacc[10] = fmaf(hA.y, a1.x, zacc[10]);
            zacc[11] = fmaf(hA.y, a1.y, zacc[11]);
            zacc[12] = fmaf(hA.y, a2.x, zacc[12]);
            zacc[13] = fmaf(hA.y, a2.y, zacc[13]);
            zacc[14] = fmaf(hA.y, a3.x, zacc[14]);
            zacc[15] = fmaf(hA.y, a3.y, zacc[15]);

            zacc[0] = fmaf(hB.x, b0.x, zacc[0]);
            zacc[1] = fmaf(hB.x, b0.y, zacc[1]);
            zacc[2] = fmaf(hB.x, b1.x, zacc[2]);
            zacc[3] = fmaf(hB.x, b1.y, zacc[3]);
            zacc[4] = fmaf(hB.x, b2.x, zacc[4]);
            zacc[5] = fmaf(hB.x, b2.y, zacc[5]);
            zacc[6] = fmaf(hB.x, b3.x, zacc[6]);
            zacc[7] = fmaf(hB.x, b3.y, zacc[7]);
            zacc[8]  = fmaf(hB.y, b0.x, zacc[8]);
            zacc[9]  = fmaf(hB.y, b0.y, zacc[9]);
            zacc[10] = fmaf(hB.y, b1.x, zacc[10]);
            zacc[11] = fmaf(hB.y, b1.y, zacc[11]);
            zacc[12] = fmaf(hB.y, b2.x, zacc[12]);
            zacc[13] = fmaf(hB.y, b2.y, zacc[13]);
            zacc[14] = fmaf(hB.y, b3.x, zacc[14]);
            zacc[15] = fmaf(hB.y, b3.y, zacc[15]);

            if (sub == 0) {
                xs[0] += a0.x + b0.x; xs[1] += a0.y + b0.y;
                xs[2] += a1.x + b1.x; xs[3] += a1.y + b1.y;
                xs[4] += a2.x + b2.x; xs[5] += a2.y + b2.y;
                xs[6] += a3.x + b3.x; xs[7] += a3.y + b3.y;
            }
        }
        if (i < o1) {
            int src = __ldg(&g_ssrc[i]);
            __half2 hh = __ldg(g_she16 + (size_t)i * 8 + sub);
            uint4 xu = __ldg((const uint4*)(g_x16 + (size_t)src * 8));
            float2 h2 = __half22float2(hh);
            __half2* ph = (__half2*)&xu;
            float2 a0 = __half22float2(ph[0]);
            float2 a1 = __half22float2(ph[1]);
            float2 a2 = __half22float2(ph[2]);
            float2 a3 = __half22float2(ph[3]);
            zacc[0] = fmaf(h2.x, a0.x, zacc[0]);
            zacc[1] = fmaf(h2.x, a0.y, zacc[1]);
            zacc[2] = fmaf(h2.x, a1.x, zacc[2]);
            zacc[3] = fmaf(h2.x, a1.y, zacc[3]);
            zacc[4] = fmaf(h2.x, a2.x, zacc[4]);
            zacc[5] = fmaf(h2.x, a2.y, zacc[5]);
            zacc[6] = fmaf(h2.x, a3.x, zacc[6]);
            zacc[7] = fmaf(h2.x, a3.y, zacc[7]);
            zacc[8]  = fmaf(h2.y, a0.x, zacc[8]);
            zacc[9]  = fmaf(h2.y, a0.y, zacc[9]);
            zacc[10] = fmaf(h2.y, a1.x, zacc[10]);
            zacc[11] = fmaf(h2.y, a1.y, zacc[11]);
            zacc[12] = fmaf(h2.y, a2.x, zacc[12]);
            zacc[13] = fmaf(h2.y, a2.y, zacc[13]);
            zacc[14] = fmaf(h2.y, a3.x, zacc[14]);
            zacc[15] = fmaf(h2.y, a3.y, zacc[15]);
            if (sub == 0) {
                xs[0] += a0.x; xs[1] += a0.y; xs[2] += a1.x; xs[3] += a1.y;
                xs[4] += a2.x; xs[5] += a2.y; xs[6] += a3.x; xs[7] += a3.y;
            }
        }

        float* zrow = sZ + gnode * ZDIM;
        #pragma unroll
        for (int f = 0; f < 8; f++) {
            zrow[j0 * 8 + f]       = zacc[f];
            zrow[(j0 + 1) * 8 + f] = zacc[8 + f];
        }
        if (sub == 0) {
            #pragma unroll
            for (int f = 0; f < 8; f++) zrow[128 + f] = xs[f];
            sInvDeg[gnode] = 1.f / fmaxf((float)(o1 - o0), 1.f);
        }
    }
    __syncthreads();

    int warp = tid >> 5, lane = tid & 31;
    int nlocbase = warp * 8;
    int nbase = nFirst + nlocbase;

    int  nn[8];
    bool valid[8];
    #pragma unroll
    for (int i = 0; i < 8; i++) {
        int nd = nbase + i;
        valid[i] = (nd < N);
        nn[i] = valid[i] ? nd : 0;
    }

    const float4* zr[8];
    #pragma unroll
    for (int i = 0; i < 8; i++)
        zr[i] = (const float4*)(sZ + (size_t)(nlocbase + i) * ZDIM);

    ull agg[8];
    #pragma unroll
    for (int i = 0; i < 8; i++) agg[i] = 0ull;

    for (int kk = 0; kk < ZDIM / 4; kk++) {
        ull wa = sWc[(4 * kk + 0) * 32 + lane];
        ull wb = sWc[(4 * kk + 1) * 32 + lane];
        ull wc = sWc[(4 * kk + 2) * 32 + lane];
        ull wd = sWc[(4 * kk + 3) * 32 + lane];
        #pragma unroll
        for (int i = 0; i < 8; i++) {
            float4 z = zr[i][kk];
            ull t;
            DUP2(t, z.x); FMA2(agg[i], t, wa);
            DUP2(t, z.y); FMA2(agg[i], t, wb);
            DUP2(t, z.z); FMA2(agg[i], t, wc);
            DUP2(t, z.w); FMA2(agg[i], t, wd);
        }
    }

    float2 ls = make_float2(0.f, 0.f), lq = make_float2(0.f, 0.f);
    #pragma unroll
    for (int i = 0; i < 8; i++) {
        float ax, ay;
        UNPACK2(ax, ay, agg[i]);
        float2 p = make_float2(sCB[2 * lane], sCB[2 * lane + 1]);
        const float* xr = x + (size_t)nn[i] * 8;
        #pragma unroll
        for (int f = 0; f < 8; f++) {
            float xv = __ldg(xr + f);
            float2 rw = sRoot[f][lane];
            p.x = fmaf(xv, rw.x, p.x);
            p.y = fmaf(xv, rw.y, p.y);
        }
        float invd = sInvDeg[nlocbase + i];
        p.x = fmaf(ax, invd, p.x);
        p.y = fmaf(ay, invd, p.y);
        if (valid[i]) {
            *(float2*)(&g_pre[(size_t)nn[i] * 64 + 2 * lane]) = p;   // STG.64
            ls.x += p.x; ls.y += p.y;
            lq.x = fmaf(p.x, p.x, lq.x);
            lq.y = fmaf(p.y, p.y, lq.y);
        }
    }
    __syncthreads();
    redS[warp * 32 + lane] = ls;
    redQ[warp * 32 + lane] = lq;
    __syncthreads();
    if (tid < 32) {
        float2 S = make_float2(0.f, 0.f), Q = make_float2(0.f, 0.f);
        #pragma unroll
        for (int w = 0; w < 8; w++) {
            S.x += redS[w * 32 + tid].x; S.y += redS[w * 32 + tid].y;
            Q.x += redQ[w * 32 + tid].x; Q.y += redQ[w * 32 + tid].y;
        }
        atomicAdd(&g_colsum[2 * tid],     S.x);
        atomicAdd(&g_colsum[2 * tid + 1], S.y);
        atomicAdd(&g_colsq[2 * tid],      Q.x);
        atomicAdd(&g_colsq[2 * tid + 1],  Q.y);
    }
}

// ---------------- layer phase helper for k_post (1024-thread blocks) ----------------
__device__ __forceinline__ void layer_phase(
    float* sIn, float* redS, float* redQ, float* sScale, float* sShift,
    const float* __restrict__ in, const float* __restrict__ w,
    const float* __restrict__ b, const float* __restrict__ gam,
    const float* __restrict__ bet, float* __restrict__ out,
    int I, int O, int nBlk)
{
    int tid = threadIdx.x;
    bool act = ((int)blockIdx.x < nBlk);
    if (act) {
        for (int idx = tid; idx < 64 * I; idx += 1024) sIn[idx] = in[idx];
    }
    __syncthreads();

    int c = tid & 31, r0 = (tid >> 5) & 7;
    int cg = blockIdx.x * 32 + c;
    bool work = act && (tid < 256);

    float acc[8];
    if (work) {
        float bv = __ldg(&b[cg]);
        #pragma unroll
        for (int i = 0; i < 8; i++) acc[i] = bv;
        for (int k = 0; k < I; k++) {
            float wv = __ldg(&w[k * O + cg]);
            #pragma unroll
            for (int i = 0; i < 8; i++)
                acc[i] = fmaf(sIn[(r0 + 8 * i) * I + k], wv, acc[i]);
        }
        float s = 0.f, q = 0.f;
        #pragma unroll
        for (int i = 0; i < 8; i++) { s += acc[i]; q = fmaf(acc[i], acc[i], q); }
        redS[r0 * 32 + c] = s;
        redQ[r0 * 32 + c] = q;
    }
    __syncthreads();
    if (act && tid < 32) {
        float S = 0.f, Q = 0.f;
        #pragma unroll
        for (int w8 = 0; w8 < 8; w8++) { S += redS[w8 * 32 + tid]; Q += redQ[w8 * 32 + tid]; }
        float m = S * (1.f / 64.f);
        float v = Q * (1.f / 64.f) - m * m;
        float r = rsqrtf(v + EPS);
        float sc = r * __ldg(&gam[blockIdx.x * 32 + tid]);
        sScale[tid] = sc;
        sShift[tid] = __ldg(&bet[blockIdx.x * 32 + tid]) - m * sc;
    }
    __syncthreads();
    if (work) {
        float sc = sScale[c], sh = sShift[c];
        #pragma unroll
        for (int i = 0; i < 8; i++)
            out[(r0 + 8 * i) * O + cg] = fmaxf(fmaf(acc[i], sc, sh), 0.f);
    }
    __syncthreads();
}

// ---------------- launch 3: post = pool | layer1 | layer2 | layer3+out ----------------
__global__ void __launch_bounds__(1024, 1)
k_post(const float* __restrict__ g_bnc, const float* __restrict__ b_bnc,
       const float* __restrict__ w1, const float* __restrict__ b1,
       const float* __restrict__ g1, const float* __restrict__ be1,
       const float* __restrict__ w2, const float* __restrict__ b2,
       const float* __restrict__ g2, const float* __restrict__ be2,
       const float* __restrict__ w3, const float* __restrict__ b3,
       const float* __restrict__ g3, const float* __restrict__ be3,
       const float* __restrict__ wout, const float* __restrict__ bout,
       float* __restrict__ out, int N) {
    extern __shared__ float sm[];                      // 64KB dynamic: layer sIn / sY
    __shared__ float redA[16][64];                     // pool sums / layer3 redS
    __shared__ float redB[16][64];                     // pool maxes / layer3 redQ
    __shared__ float sScale[64], sShift[64];
    __shared__ float redS[8 * 32], redQ[8 * 32];       // layer1/2 reductions

    int tid = threadIdx.x, b = blockIdx.x;
    if (b == 0 && tid < 2) g_ctr[tid] = 0;             // reset k_prep's barrier counters

    // ---- pool (per-graph, 64 blocks) ----
    if (tid < 64) {
        float invN = 1.f / (float)N;
        float m = g_colsum[tid] * invN;
        float v = g_colsq[tid] * invN - m * m;
        float r = rsqrtf(v + EPS);
        float sc = r * __ldg(&g_bnc[tid]);
        sScale[tid] = sc;
        sShift[tid] = __ldg(&b_bnc[tid]) - m * sc;
    }
    __syncthreads();
    {
        int rg = tid >> 6;       // 0..15
        int c  = tid & 63;
        int s0 = g_start[b], s1 = g_start[b + 1];
        float sc = sScale[c], sh = sShift[c];
        float sum = 0.f, mx = 0.f;
        for (int n = s0 + rg; n < s1; n += 16) {
            float p = __ldg(&g_pre[(size_t)n * 64 + c]);
            float h = fmaxf(fmaf(p, sc, sh), 0.f);
            sum += h;
            mx = fmaxf(mx, h);
        }
        redA[rg][c] = sum;
        redB[rg][c] = mx;
        __syncthreads();
        if (tid < 64) {
            float S = 0.f, M = 0.f;
            #pragma unroll
            for (int r = 0; r < 16; r++) { S += redA[r][tid]; M = fmaxf(M, redB[r][tid]); }
            int cnt = s1 - s0;
            g_gfeat[b * 128 + tid]      = S / fmaxf((float)cnt, 1.f);
            g_gfeat[b * 128 + 64 + tid] = (cnt > 0) ? M : 0.f;
            g_colsum[tid] = 0.f;       // reset for next replay
            g_colsq[tid]  = 0.f;
        }
    }
    grid_barrier(&g_ctr[2], GRAPHS);

    // ---- layer1: 8 blocks, I=128 O=256 ----
    layer_phase(sm, redS, redQ, sScale, sShift, g_gfeat, w1, b1, g1, be1, g_y1, 128, 256, 8);
    grid_barrier(&g_ctr[3], GRAPHS);

    // ---- layer2: 4 blocks, I=256 O=128 ----
    layer_phase(sm, redS, redQ, sScale, sShift, g_y1, w2, b2, g2, be2, g_y2, 256, 128, 4);
    grid_barrier(&g_ctr[4], GRAPHS);

    // ---- layer3 + final projection (block 0) ----
    if (b == 0) {
        float* sIn = sm;              // 64*128 floats
        float* sY  = sm + 64 * 128;   // 64*64 floats
        for (int idx = tid; idx < 64 * 128; idx += 1024) sIn[idx] = g_y2[idx];
        __syncthreads();

        int c = tid & 63, r0 = (tid >> 6) & 7;
        bool work = (tid < 512);
        float acc[8];
        if (work) {
            float bv = __ldg(&b3[c]);
            #pragma unroll
            for (int i = 0; i < 8; i++) acc[i] = bv;
            for (int k = 0; k < 128; k++) {
                float wv = __ldg(&w3[k * 64 + c]);
                #pragma unroll
                for (int i = 0; i < 8; i++)
                    acc[i] = fmaf(sIn[(r0 + 8 * i) * 128 + k], wv, acc[i]);
            }
            float s = 0.f, q = 0.f;
            #pragma unroll
            for (int i = 0; i < 8; i++) { s += acc[i]; q = fmaf(acc[i], acc[i], q); }
            redA[r0][c] = s;
            redB[r0][c] = q;
        }
        __syncthreads();
        if (tid < 64) {
            float S = 0.f, Q = 0.f;
            #pragma unroll
            for (int r = 0; r < 8; r++) { S += redA[r][tid]; Q += redB[r][tid]; }
            float m = S * (1.f / 64.f);
            float v = Q * (1.f / 64.f) - m * m;
            float r2 = rsqrtf(v + EPS);
            float sc = r2 * __ldg(&g3[tid]);
            sScale[tid] = sc;
            sShift[tid] = __ldg(&be3[tid]) - m * sc;
        }
        __syncthreads();
        if (work) {
            float sc = sScale[c], sh = sShift[c];
            #pragma unroll
            for (int i = 0; i < 8; i++)
                sY[(r0 + 8 * i) * 64 + c] = fmaxf(fmaf(acc[i], sc, sh), 0.f);
        }
        __syncthreads();
        for (int t = tid; t < GRAPHS * 10; t += 1024) {
            int g = t / 10, o = t % 10;
            float s2 = __ldg(&bout[o]);
            #pragma unroll
            for (int k = 0; k < 64; k++)
                s2 = fmaf(sY[g * 64 + k], __ldg(&wout[k * 10 + o]), s2);
            out[t] = s2;
        }
    }
}

// ---------------- launch ----------------
extern "C" void kernel_launch(void* const* d_in, const int* in_sizes, int n_in,
                              void* d_out, int out_size) {
    const float* x      = (const float*)d_in[0];
    const int*   ei     = (const int*)  d_in[1];
    const float* ea     = (const float*)d_in[2];
    const int*   batch  = (const int*)  d_in[3];
    const float* w_e1   = (const float*)d_in[4];
    const float* b_e1   = (const float*)d_in[5];
    const float* w_e2   = (const float*)d_in[6];
    const float* b_e2   = (const float*)d_in[7];
    const float* root   = (const float*)d_in[8];
    const float* cbias  = (const float*)d_in[9];
    const float* g_bnc  = (const float*)d_in[10];
    const float* b_bnc  = (const float*)d_in[11];
    const float* w1     = (const float*)d_in[12];
    const float* b1     = (const float*)d_in[13];
    const float* g1     = (const float*)d_in[14];
    const float* be1    = (const float*)d_in[15];
    const float* w2     = (const float*)d_in[16];
    const float* b2     = (const float*)d_in[17];
    const float* g2     = (const float*)d_in[18];
    const float* be2    = (const float*)d_in[19];
    const float* w3     = (const float*)d_in[20];
    const float* b3     = (const float*)d_in[21];
    const float* g3     = (const float*)d_in[22];
    const float* be3    = (const float*)d_in[23];
    const float* wout   = (const float*)d_in[24];
    const float* bout   = (const float*)d_in[25];

    int N = in_sizes[0] / 8;
    int E = in_sizes[2] / 8;
    if (N > NMAX) N = NMAX;
    if (E > EMAX) E = EMAX;

    const int fusedSmem = ZDIM * 32 * 8 + 64 * ZDIM * 4;     // 69632 B
    const int postSmem  = 64 * 256 * (int)sizeof(float);     // 65536 B
    cudaFuncSetAttribute(k_fused, cudaFuncAttributeMaxDynamicSharedMemorySize, fusedSmem);
    cudaFuncSetAttribute(k_post,  cudaFuncAttributeMaxDynamicSharedMemorySize, postSmem);

    k_prep<<<PREP_B, PREP_T>>>(ei, batch, x, ea, w_e1, b_e1, N, E);
    k_fused<<<(N + 63) / 64, 256, fusedSmem>>>(x, w_e2, b_e2, root, cbias, N);
    k_post<<<GRAPHS, 1024, postSmem>>>(g_bnc, b_bnc, w1, b1, g1, be1,
                                       w2, b2, g2, be2, w3, b3, g3, be3,
                                       wout, bout, (float*)d_out, N);
}

// round 14
// speedup vs baseline: 1.6894x; 1.0117x over previous
#include <cuda_runtime.h>
#include <cuda_fp16.h>
#include <cstdint>

#define NMAX   50000
#define EMAX   500000
#define ZDIM   136      // 16 (he) x 8 (x) + 8 (x bias lanes)
#define GRAPHS 64
#define EPS    1e-5f
#define PREP_B 256
#define PREP_T 512

typedef unsigned long long ull;

// packed fp32x2 helpers (Blackwell FFMA2)
#define DUP2(d, s)    asm("mov.b64 %0, {%1, %1};" : "=l"(d) : "f"(s))
#define FMA2(d, a, b) asm("fma.rn.f32x2 %0, %1, %2, %0;" : "+l"(d) : "l"(a), "l"(b))
#define PACK2(d, lo, hi) asm("mov.b64 %0, {%1, %2};" : "=l"(d) : "f"(lo), "f"(hi))
#define UNPACK2(lo, hi, s) asm("mov.b64 {%0, %1}, %2;" : "=f"(lo), "=f"(hi) : "l"(s))

// ---------------- scratch (device globals; zero-initialized at load) ----------------
__device__ int      g_cnt[NMAX];                    // degree histogram (re-zeroed by scan phase)
__device__ int      g_off[NMAX + 1];                // CSR offsets
__device__ int      g_cur[NMAX];                    // scatter cursors
__device__ int      g_bsum[PREP_B];                 // scan block totals+1 (re-zeroed in prepB)
__device__ int      g_ctr[8];                       // grid-barrier counters (cross-reset by kernels)
__device__ int      g_ssrc[EMAX];                   // dst-sorted src ids
__device__ __half2  g_she16[(size_t)EMAX * 8];      // dst-sorted he vectors (fp16, 32 B/edge)
__device__ __half   g_x16[(size_t)NMAX * 8];        // fp16 copy of x (16 B/node)
__device__ float    g_pre[(size_t)NMAX * 64];       // NNConv pre-BN output
__device__ float    g_colsum[64];                   // (re-zeroed in k_post)
__device__ float    g_colsq[64];
__device__ int      g_start[GRAPHS + 1];            // graph boundaries
__device__ float    g_gfeat[GRAPHS * 128];
__device__ float    g_y1[GRAPHS * 256];
__device__ float    g_y2[GRAPHS * 128];

// ---------------- grid-wide barrier (all blocks co-resident) ----------------
__device__ __forceinline__ void grid_barrier(int* ctr, int target) {
    __threadfence();
    __syncthreads();
    if (threadIdx.x == 0) {
        atomicAdd(ctr, 1);
        while (atomicAdd(ctr, 0) < target) { __nanosleep(64); }
    }
    __syncthreads();
}

// ---------------- launch 1: prepA = hist + boundaries + x16 | barrier | scan ----------------
__global__ void __launch_bounds__(PREP_T, 2)
k_prepA(const int* __restrict__ ei,
        const int* __restrict__ batch,
        const float* __restrict__ x,
        int N, int E) {
    __shared__ int sv[PREP_T];
    __shared__ int sred[PREP_T];

    int tid = threadIdx.x, b = blockIdx.x;
    int gsz = gridDim.x * blockDim.x;
    int gid = b * blockDim.x + tid;

    if (b == 0 && tid < 3) g_ctr[2 + tid] = 0;   // reset k_post's barrier counters

    // ---- phase A: histogram + graph boundaries + x -> fp16 ----
    int cover = (E > N) ? E : N;
    for (int i = gid; i < cover; i += gsz) {
        if (i < E) atomicAdd(&g_cnt[__ldg(&ei[E + i])], 1);
        if (i < N) {
            int bn = __ldg(&batch[i]);
            int bp = (i == 0) ? -1 : __ldg(&batch[i - 1]);
            for (int g = bp + 1; g <= bn; g++) g_start[g] = i;
            if (i == N - 1) {
                for (int g = bn + 1; g <= GRAPHS; g++) g_start[g] = N;
            }
            float4 x0 = __ldg((const float4*)(x + (size_t)i * 8));
            float4 x1 = __ldg((const float4*)(x + (size_t)i * 8 + 4));
            __half2 h[4];
            h[0] = __floats2half2_rn(x0.x, x0.y);
            h[1] = __floats2half2_rn(x0.z, x0.w);
            h[2] = __floats2half2_rn(x1.x, x1.y);
            h[3] = __floats2half2_rn(x1.z, x1.w);
            *(uint4*)(g_x16 + (size_t)i * 8) = *(uint4*)h;
        }
    }
    grid_barrier(&g_ctr[0], PREP_B);

    // ---- phase B: scan (decoupled block totals) ----
    {
        int C = (N + PREP_B - 1) / PREP_B;
        int base0 = b * C, end = min(base0 + C, N);
        int run = 0;
        for (int t0 = base0; t0 < end; t0 += PREP_T) {
            int idx = t0 + tid;
            int v = 0;
            if (idx < end) { v = g_cnt[idx]; g_cnt[idx] = 0; }   // read + reset for next replay
            sv[tid] = v;
            __syncthreads();
            for (int off = 1; off < PREP_T; off <<= 1) {
                int u = (tid >= off) ? sv[tid - off] : 0;
                __syncthreads();
                sv[tid] += u;
                __syncthreads();
            }
            if (idx < end) g_off[idx] = run + sv[tid] - v;       // local exclusive
            run += sv[PREP_T - 1];
            __syncthreads();
        }
        if (tid == 0) atomicExch(&g_bsum[b], run + 1);
        int v = 0;
        if (tid < b) {
            while ((v = atomicAdd(&g_bsum[tid], 0)) == 0) { }
            v -= 1;
        }
        sred[tid] = v;
        __syncthreads();
        for (int off = PREP_T / 2; off > 0; off >>= 1) {
            if (tid < off) sred[tid] += sred[tid + off];
            __syncthreads();
        }
        int base = sred[0];
        for (int idx = base0 + tid; idx < end; idx += PREP_T) {
            int o = g_off[idx] + base;
            g_off[idx] = o;
            g_cur[idx] = o;
        }
        if (b == PREP_B - 1 && tid == 0) g_off[N] = E;
    }
}

// ---------------- launch 2: prepB = edge MLP + scatter (he fp16 at sorted pos) ----------------
__global__ void __launch_bounds__(PREP_T, 2)
k_prepB(const int* __restrict__ ei,
        const float* __restrict__ ea,
        const float* __restrict__ w_e1,
        const float* __restrict__ b_e1,
        int E) {
    __shared__ float sW1[128];
    __shared__ float sB1[16];

    int tid = threadIdx.x, b = blockIdx.x;
    int gsz = gridDim.x * blockDim.x;
    int gid = b * blockDim.x + tid;

    if (tid < 128) sW1[tid] = w_e1[tid];
    if (tid < 16)  sB1[tid] = b_e1[tid];
    if (b == 0 && tid < PREP_B) g_bsum[tid] = 0;   // reset for next replay
    __syncthreads();

    for (int e = gid; e < E; e += gsz) {
        int src = __ldg(&ei[e]);
        int dst = __ldg(&ei[E + e]);
        float4 a0 = __ldg((const float4*)(ea + (size_t)e * 8));
        float4 a1 = __ldg((const float4*)(ea + (size_t)e * 8 + 4));

        __half2 hp[8];
        #pragma unroll
        for (int p = 0; p < 8; p++) {
            float s0 = sB1[2 * p], s1 = sB1[2 * p + 1];
            s0 = fmaf(a0.x, sW1[0 * 16 + 2 * p], s0); s1 = fmaf(a0.x, sW1[0 * 16 + 2 * p + 1], s1);
            s0 = fmaf(a0.y, sW1[1 * 16 + 2 * p], s0); s1 = fmaf(a0.y, sW1[1 * 16 + 2 * p + 1], s1);
            s0 = fmaf(a0.z, sW1[2 * 16 + 2 * p], s0); s1 = fmaf(a0.z, sW1[2 * 16 + 2 * p + 1], s1);
            s0 = fmaf(a0.w, sW1[3 * 16 + 2 * p], s0); s1 = fmaf(a0.w, sW1[3 * 16 + 2 * p + 1], s1);
            s0 = fmaf(a1.x, sW1[4 * 16 + 2 * p], s0); s1 = fmaf(a1.x, sW1[4 * 16 + 2 * p + 1], s1);
            s0 = fmaf(a1.y, sW1[5 * 16 + 2 * p], s0); s1 = fmaf(a1.y, sW1[5 * 16 + 2 * p + 1], s1);
            s0 = fmaf(a1.z, sW1[6 * 16 + 2 * p], s0); s1 = fmaf(a1.z, sW1[6 * 16 + 2 * p + 1], s1);
            s0 = fmaf(a1.w, sW1[7 * 16 + 2 * p], s0); s1 = fmaf(a1.w, sW1[7 * 16 + 2 * p + 1], s1);
            hp[p] = __floats2half2_rn(fmaxf(s0, 0.f), fmaxf(s1, 0.f));
        }

        int pos = atomicAdd(&g_cur[dst], 1);
        uint4* hr = (uint4*)(g_she16 + (size_t)pos * 8);
        hr[0] = *(uint4*)&hp[0];
        hr[1] = *(uint4*)&hp[4];
        g_ssrc[pos] = src;
    }
}

// ---------------- launch 3: fused z-accumulate + node GEMM (f32x2) + BN stats ----------------
// block = 256 threads, 64 nodes, 3 blocks/SM. (byte-identical to R13)
__global__ void __launch_bounds__(256, 3)
k_fused(const float* __restrict__ x,
        const float* __restrict__ w_e2,
        const float* __restrict__ b_e2,
        const float* __restrict__ root,
        const float* __restrict__ cbias,
        int N) {
    extern __shared__ char dynsmem[];
    ull*   sWc = (ull*)dynsmem;                          // [136][32] packed col pairs = 34816 B
    float* sZ  = (float*)(dynsmem + ZDIM * 32 * 8);      // [64][136] = 34816 B
    float2* redS = (float2*)sZ;                          // aliased after z reads complete
    float2* redQ = (float2*)(sZ + 512);

    __shared__ float2 sRoot[8][32];
    __shared__ float  sCB[64];
    __shared__ float  sInvDeg[64];

    int tid = threadIdx.x;

    for (int idx = tid; idx < ZDIM * 32; idx += blockDim.x) {
        int k = idx >> 5, l = idx & 31;
        int h0 = 2 * l;
        float a, b;
        if (k < 128) {
            int j = k >> 3, f = k & 7;
            a = w_e2[j * 512 + f * 64 + h0];
            b = w_e2[j * 512 + f * 64 + h0 + 1];
        } else {
            int f = k - 128;
            a = b_e2[f * 64 + h0];
            b = b_e2[f * 64 + h0 + 1];
        }
        ull u; PACK2(u, a, b);
        sWc[k * 32 + l] = u;
    }
    for (int idx = tid; idx < 8 * 32; idx += blockDim.x) {
        int f = idx >> 5, l = idx & 31;
        sRoot[f][l] = make_float2(root[f * 64 + 2 * l], root[f * 64 + 2 * l + 1]);
    }
    if (tid < 64) sCB[tid] = cbias[tid];

    int nFirst = blockIdx.x * 64;

    for (int half = 0; half < 2; half++) {
        int gnode = half * 32 + (tid >> 3);
        int sub   = tid & 7;
        int n = nFirst + gnode;
        int j0 = 2 * sub;
        int o0 = 0, o1 = 0;
        if (n < N) {
            o0 = __ldg(&g_off[n]);
            o1 = __ldg(&g_off[n + 1]);
        }

        float zacc[16];
        #pragma unroll
        for (int i = 0; i < 16; i++) zacc[i] = 0.f;
        float xs[8];
        #pragma unroll
        for (int i = 0; i < 8; i++) xs[i] = 0.f;

        int i = o0;
        int sA = 0, sB = 0;
        __half2 hA2, hB2;
        if (i + 2 <= o1) {
            sA  = __ldg(&g_ssrc[i]);
            sB  = __ldg(&g_ssrc[i + 1]);
            hA2 = __ldg(g_she16 + (size_t)i * 8 + sub);
            hB2 = __ldg(g_she16 + (size_t)(i + 1) * 8 + sub);
        }
        for (; i + 2 <= o1; i += 2) {
            uint4 xAu = __ldg((const uint4*)(g_x16 + (size_t)sA * 8));
            uint4 xBu = __ldg((const uint4*)(g_x16 + (size_t)sB * 8));
            float2 hA = __half22float2(hA2);
            float2 hB = __half22float2(hB2);

            int ip = (i + 4 <= o1) ? i + 2 : i;
            sA  = __ldg(&g_ssrc[ip]);
            sB  = __ldg(&g_ssrc[ip + 1]);
            hA2 = __ldg(g_she16 + (size_t)ip * 8 + sub);
            hB2 = __ldg(g_she16 + (size_t)(ip + 1) * 8 + sub);

            __half2* phA = (__half2*)&xAu;
            __half2* phB = (__half2*)&xBu;
            float2 a0 = __half22float2(phA[0]);
            float2 a1 = __half22float2(phA[1]);
            float2 a2 = __half22float2(phA[2]);
            float2 a3 = __half22float2(phA[3]);
            float2 b0 = __half22float2(phB[0]);
            float2 b1 = __half22float2(phB[1]);
            float2 b2 = __half22float2(phB[2]);
            float2 b3 = __half22float2(phB[3]);

            zacc[0] = fmaf(hA.x, a0.x, zacc[0]);
            zacc[1] = fmaf(hA.x, a0.y, zacc[1]);
            zacc[2] = fmaf(hA.x, a1.x, zacc[2]);
            zacc[3] = fmaf(hA.x, a1.y, zacc[3]);
            zacc[4] = fmaf(hA.x, a2.x, zacc[4]);
            zacc[5] = fmaf(hA.x, a2.y, zacc[5]);
            zacc[6] = fmaf(hA.x, a3.x, zacc[6]);
            zacc[7] = fmaf(hA.x, a3.y, zacc[7]);
            zacc[8]  = fmaf(hA.y, a0.x, zacc[8]);
            zacc[9]  = fmaf(hA.y, a0.y, zacc[9]);
            zacc[10] = fmaf(hA.y, a1.x, zacc[10]);
            zacc[11] = fmaf(hA.y, a1.y, zacc[11]);
            zacc[12] = fmaf(hA.y, a2.x, zacc[12]);
            zacc[13] = fmaf(hA.y, a2.y, zacc[13]);
            zacc[14] = fmaf(hA.y, a3.x, zacc[14]);
            zacc[15] = fmaf(hA.y, a3.y, zacc[15]);

            zacc[0] = fmaf(hB.x, b0.x, zacc[0]);
            zacc[1] = fmaf(hB.x, b0.y, zacc[1]);
            zacc[2] = fmaf(hB.x, b1.x, zacc[2]);
            zacc[3] = fmaf(hB.x, b1.y, zacc[3]);
            zacc[4] = fmaf(hB.x, b2.x, zacc[4]);
            zacc[5] = fmaf(hB.x, b2.y, zacc[5]);
            zacc[6] = fmaf(hB.x, b3.x, zacc[6]);
            zacc[7] = fmaf(hB.x, b3.y, zacc[7]);
            zacc[8]  = fmaf(hB.y, b0.x, zacc[8]);
            zacc[9]  = fmaf(hB.y, b0.y, zacc[9]);
            zacc[10] = fmaf(hB.y, b1.x, zacc[10]);
            zacc[11] = fmaf(hB.y, b1.y, zacc[11]);
            zacc[12] = fmaf(hB.y, b2.x, zacc[12]);
            zacc[13] = fmaf(hB.y, b2.y, zacc[13]);
            zacc[14] = fmaf(hB.y, b3.x, zacc[14]);
            zacc[15] = fmaf(hB.y, b3.y, zacc[15]);

            if (sub == 0) {
                xs[0] += a0.x + b0.x; xs[1] += a0.y + b0.y;
                xs[2] += a1.x + b1.x; xs[3] += a1.y + b1.y;
                xs[4] += a2.x + b2.x; xs[5] += a2.y + b2.y;
                xs[6] += a3.x + b3.x; xs[7] += a3.y + b3.y;
            }
        }
        if (i < o1) {
            int src = __ldg(&g_ssrc[i]);
            __half2 hh = __ldg(g_she16 + (size_t)i * 8 + sub);
            uint4 xu = __ldg((const uint4*)(g_x16 + (size_t)src * 8));
            float2 h2 = __half22float2(hh);
            __half2* ph = (__half2*)&xu;
            float2 a0 = __half22float2(ph[0]);
            float2 a1 = __half22float2(ph[1]);
            float2 a2 = __half22float2(ph[2]);
            float2 a3 = __half22float2(ph[3]);
            zacc[0] = fmaf(h2.x, a0.x, zacc[0]);
            zacc[1] = fmaf(h2.x, a0.y, zacc[1]);
            zacc[2] = fmaf(h2.x, a1.x, zacc[2]);
            zacc[3] = fmaf(h2.x, a1.y, zacc[3]);
            zacc[4] = fmaf(h2.x, a2.x, zacc[4]);
            zacc[5] = fmaf(h2.x, a2.y, zacc[5]);
            zacc[6] = fmaf(h2.x, a3.x, zacc[6]);
            zacc[7] = fmaf(h2.x, a3.y, zacc[7]);
            zacc[8]  = fmaf(h2.y, a0.x, zacc[8]);
            zacc[9]  = fmaf(h2.y, a0.y, zacc[9]);
            zacc[10] = fmaf(h2.y, a1.x, zacc[10]);
            zacc[11] = fmaf(h2.y, a1.y, zacc[11]);
            zacc[12] = fmaf(h2.y, a2.x, zacc[12]);
            zacc[13] = fmaf(h2.y, a2.y, zacc[13]);
            zacc[14] = fmaf(h2.y, a3.x, zacc[14]);
            zacc[15] = fmaf(h2.y, a3.y, zacc[15]);
            if (sub == 0) {
                xs[0] += a0.x; xs[1] += a0.y; xs[2] += a1.x; xs[3] += a1.y;
                xs[4] += a2.x; xs[5] += a2.y; xs[6] += a3.x; xs[7] += a3.y;
            }
        }

        float* zrow = sZ + gnode * ZDIM;
        #pragma unroll
        for (int f = 0; f < 8; f++) {
            zrow[j0 * 8 + f]       = zacc[f];
            zrow[(j0 + 1) * 8 + f] = zacc[8 + f];
        }
        if (sub == 0) {
            #pragma unroll
            for (int f = 0; f < 8; f++) zrow[128 + f] = xs[f];
            sInvDeg[gnode] = 1.f / fmaxf((float)(o1 - o0), 1.f);
        }
    }
    __syncthreads();

    int warp = tid >> 5, lane = tid & 31;
    int nlocbase = warp * 8;
    int nbase = nFirst + nlocbase;

    int  nn[8];
    bool valid[8];
    #pragma unroll
    for (int i = 0; i < 8; i++) {
        int nd = nbase + i;
        valid[i] = (nd < N);
        nn[i] = valid[i] ? nd : 0;
    }

    const float4* zr[8];
    #pragma unroll
    for (int i = 0; i < 8; i++)
        zr[i] = (const float4*)(sZ + (size_t)(nlocbase + i) * ZDIM);

    ull agg[8];
    #pragma unroll
    for (int i = 0; i < 8; i++) agg[i] = 0ull;

    for (int kk = 0; kk < ZDIM / 4; kk++) {
        ull wa = sWc[(4 * kk + 0) * 32 + lane];
        ull wb = sWc[(4 * kk + 1) * 32 + lane];
        ull wc = sWc[(4 * kk + 2) * 32 + lane];
        ull wd = sWc[(4 * kk + 3) * 32 + lane];
        #pragma unroll
        for (int i = 0; i < 8; i++) {
            float4 z = zr[i][kk];
            ull t;
            DUP2(t, z.x); FMA2(agg[i], t, wa);
            DUP2(t, z.y); FMA2(agg[i], t, wb);
            DUP2(t, z.z); FMA2(agg[i], t, wc);
            DUP2(t, z.w); FMA2(agg[i], t, wd);
        }
    }

    float2 ls = make_float2(0.f, 0.f), lq = make_float2(0.f, 0.f);
    #pragma unroll
    for (int i = 0; i < 8; i++) {
        float ax, ay;
        UNPACK2(ax, ay, agg[i]);
        float2 p = make_float2(sCB[2 * lane], sCB[2 * lane + 1]);
        const float* xr = x + (size_t)nn[i] * 8;
        #pragma unroll
        for (int f = 0; f < 8; f++) {
            float xv = __ldg(xr + f);
            float2 rw = sRoot[f][lane];
            p.x = fmaf(xv, rw.x, p.x);
            p.y = fmaf(xv, rw.y, p.y);
        }
        float invd = sInvDeg[nlocbase + i];
        p.x = fmaf(ax, invd, p.x);
        p.y = fmaf(ay, invd, p.y);
        if (valid[i]) {
            *(float2*)(&g_pre[(size_t)nn[i] * 64 + 2 * lane]) = p;   // STG.64
            ls.x += p.x; ls.y += p.y;
            lq.x = fmaf(p.x, p.x, lq.x);
            lq.y = fmaf(p.y, p.y, lq.y);
        }
    }
    __syncthreads();
    redS[warp * 32 + lane] = ls;
    redQ[warp * 32 + lane] = lq;
    __syncthreads();
    if (tid < 32) {
        float2 S = make_float2(0.f, 0.f), Q = make_float2(0.f, 0.f);
        #pragma unroll
        for (int w = 0; w < 8; w++) {
            S.x += redS[w * 32 + tid].x; S.y += redS[w * 32 + tid].y;
            Q.x += redQ[w * 32 + tid].x; Q.y += redQ[w * 32 + tid].y;
        }
        atomicAdd(&g_colsum[2 * tid],     S.x);
        atomicAdd(&g_colsum[2 * tid + 1], S.y);
        atomicAdd(&g_colsq[2 * tid],      Q.x);
        atomicAdd(&g_colsq[2 * tid + 1],  Q.y);
    }
}

// ---------------- layer phase helper for k_post (1024-thread blocks) ----------------
__device__ __forceinline__ void layer_phase(
    float* sIn, float* redS, float* redQ, float* sScale, float* sShift,
    const float* __restrict__ in, const float* __restrict__ w,
    const float* __restrict__ b, const float* __restrict__ gam,
    const float* __restrict__ bet, float* __restrict__ out,
    int I, int O, int nBlk)
{
    int tid = threadIdx.x;
    bool act = ((int)blockIdx.x < nBlk);
    if (act) {
        for (int idx = tid; idx < 64 * I; idx += 1024) sIn[idx] = in[idx];
    }
    __syncthreads();

    int c = tid & 31, r0 = (tid >> 5) & 7;
    int cg = blockIdx.x * 32 + c;
    bool work = act && (tid < 256);

    float acc[8];
    if (work) {
        float bv = __ldg(&b[cg]);
        #pragma unroll
        for (int i = 0; i < 8; i++) acc[i] = bv;
        for (int k = 0; k < I; k++) {
            float wv = __ldg(&w[k * O + cg]);
            #pragma unroll
            for (int i = 0; i < 8; i++)
                acc[i] = fmaf(sIn[(r0 + 8 * i) * I + k], wv, acc[i]);
        }
        float s = 0.f, q = 0.f;
        #pragma unroll
        for (int i = 0; i < 8; i++) { s += acc[i]; q = fmaf(acc[i], acc[i], q); }
        redS[r0 * 32 + c] = s;
        redQ[r0 * 32 + c] = q;
    }
    __syncthreads();
    if (act && tid < 32) {
        float S = 0.f, Q = 0.f;
        #pragma unroll
        for (int w8 = 0; w8 < 8; w8++) { S += redS[w8 * 32 + tid]; Q += redQ[w8 * 32 + tid]; }
        float m = S * (1.f / 64.f);
        float v = Q * (1.f / 64.f) - m * m;
        float r = rsqrtf(v + EPS);
        float sc = r * __ldg(&gam[blockIdx.x * 32 + tid]);
        sScale[tid] = sc;
        sShift[tid] = __ldg(&bet[blockIdx.x * 32 + tid]) - m * sc;
    }
    __syncthreads();
    if (work) {
        float sc = sScale[c], sh = sShift[c];
        #pragma unroll
        for (int i = 0; i < 8; i++)
            out[(r0 + 8 * i) * O + cg] = fmaxf(fmaf(acc[i], sc, sh), 0.f);
    }
    __syncthreads();
}

// ---------------- launch 4 (profiled): post = pool | layer1 | layer2 | layer3+out ----------------
__global__ void __launch_bounds__(1024, 1)
k_post(const float* __restrict__ g_bnc, const float* __restrict__ b_bnc,
       const float* __restrict__ w1, const float* __restrict__ b1,
       const float* __restrict__ g1, const float* __restrict__ be1,
       const float* __restrict__ w2, const float* __restrict__ b2,
       const float* __restrict__ g2, const float* __restrict__ be2,
       const float* __restrict__ w3, const float* __restrict__ b3,
       const float* __restrict__ g3, const float* __restrict__ be3,
       const float* __restrict__ wout, const float* __restrict__ bout,
       float* __restrict__ out, int N) {
    extern __shared__ float sm[];                      // 64KB dynamic: layer sIn / sY
    __shared__ float redA[16][64];                     // pool sums / layer3 redS
    __shared__ float redB[16][64];                     // pool maxes / layer3 redQ
    __shared__ float sScale[64], sShift[64];
    __shared__ float redS[8 * 32], redQ[8 * 32];       // layer1/2 reductions

    int tid = threadIdx.x, b = blockIdx.x;
    if (b == 0 && tid == 0) g_ctr[0] = 0;              // reset k_prepA's barrier counter

    // ---- pool (per-graph, 64 blocks) ----
    if (tid < 64) {
        float invN = 1.f / (float)N;
        float m = g_colsum[tid] * invN;
        float v = g_colsq[tid] * invN - m * m;
        float r = rsqrtf(v + EPS);
        float sc = r * __ldg(&g_bnc[tid]);
        sScale[tid] = sc;
        sShift[tid] = __ldg(&b_bnc[tid]) - m * sc;
    }
    __syncthreads();
    {
        int rg = tid >> 6;       // 0..15
        int c  = tid & 63;
        int s0 = g_start[b], s1 = g_start[b + 1];
        float sc = sScale[c], sh = sShift[c];
        float sum = 0.f, mx = 0.f;
        for (int n = s0 + rg; n < s1; n += 16) {
            float p = __ldg(&g_pre[(size_t)n * 64 + c]);
            float h = fmaxf(fmaf(p, sc, sh), 0.f);
            sum += h;
            mx = fmaxf(mx, h);
        }
        redA[rg][c] = sum;
        redB[rg][c] = mx;
        __syncthreads();
        if (tid < 64) {
            float S = 0.f, M = 0.f;
            #pragma unroll
            for (int r = 0; r < 16; r++) { S += redA[r][tid]; M = fmaxf(M, redB[r][tid]); }
            int cnt = s1 - s0;
            g_gfeat[b * 128 + tid]      = S / fmaxf((float)cnt, 1.f);
            g_gfeat[b * 128 + 64 + tid] = (cnt > 0) ? M : 0.f;
            g_colsum[tid] = 0.f;       // reset for next replay
            g_colsq[tid]  = 0.f;
        }
    }
    grid_barrier(&g_ctr[2], GRAPHS);

    // ---- layer1: 8 blocks, I=128 O=256 ----
    layer_phase(sm, redS, redQ, sScale, sShift, g_gfeat, w1, b1, g1, be1, g_y1, 128, 256, 8);
    grid_barrier(&g_ctr[3], GRAPHS);

    // ---- layer2: 4 blocks, I=256 O=128 ----
    layer_phase(sm, redS, redQ, sScale, sShift, g_y1, w2, b2, g2, be2, g_y2, 256, 128, 4);
    grid_barrier(&g_ctr[4], GRAPHS);

    // ---- layer3 + final projection (block 0) ----
    if (b == 0) {
        float* sIn = sm;              // 64*128 floats
        float* sY  = sm + 64 * 128;   // 64*64 floats
        for (int idx = tid; idx < 64 * 128; idx += 1024) sIn[idx] = g_y2[idx];
        __syncthreads();

        int c = tid & 63, r0 = (tid >> 6) & 7;
        bool work = (tid < 512);
        float acc[8];
        if (work) {
            float bv = __ldg(&b3[c]);
            #pragma unroll
            for (int i = 0; i < 8; i++) acc[i] = bv;
            for (int k = 0; k < 128; k++) {
                float wv = __ldg(&w3[k * 64 + c]);
                #pragma unroll
                for (int i = 0; i < 8; i++)
                    acc[i] = fmaf(sIn[(r0 + 8 * i) * 128 + k], wv, acc[i]);
            }
            float s = 0.f, q = 0.f;
            #pragma unroll
            for (int i = 0; i < 8; i++) { s += acc[i]; q = fmaf(acc[i], acc[i], q); }
            redA[r0][c] = s;
            redB[r0][c] = q;
        }
        __syncthreads();
        if (tid < 64) {
            float S = 0.f, Q = 0.f;
            #pragma unroll
            for (int r = 0; r < 8; r++) { S += redA[r][tid]; Q += redB[r][tid]; }
            float m = S * (1.f / 64.f);
            float v = Q * (1.f / 64.f) - m * m;
            float r2 = rsqrtf(v + EPS);
            float sc = r2 * __ldg(&g3[tid]);
            sScale[tid] = sc;
            sShift[tid] = __ldg(&be3[tid]) - m * sc;
        }
        __syncthreads();
        if (work) {
            float sc = sScale[c], sh = sShift[c];
            #pragma unroll
            for (int i = 0; i < 8; i++)
                sY[(r0 + 8 * i) * 64 + c] = fmaxf(fmaf(acc[i], sc, sh), 0.f);
        }
        __syncthreads();
        for (int t = tid; t < GRAPHS * 10; t += 1024) {
            int g = t / 10, o = t % 10;
            float s2 = __ldg(&bout[o]);
            #pragma unroll
            for (int k = 0; k < 64; k++)
                s2 = fmaf(sY[g * 64 + k], __ldg(&wout[k * 10 + o]), s2);
            out[t] = s2;
        }
    }
}

// ---------------- launch ----------------
extern "C" void kernel_launch(void* const* d_in, const int* in_sizes, int n_in,
                              void* d_out, int out_size) {
    const float* x      = (const float*)d_in[0];
    const int*   ei     = (const int*)  d_in[1];
    const float* ea     = (const float*)d_in[2];
    const int*   batch  = (const int*)  d_in[3];
    const float* w_e1   = (const float*)d_in[4];
    const float* b_e1   = (const float*)d_in[5];
    const float* w_e2   = (const float*)d_in[6];
    const float* b_e2   = (const float*)d_in[7];
    const float* root   = (const float*)d_in[8];
    const float* cbias  = (const float*)d_in[9];
    const float* g_bnc  = (const float*)d_in[10];
    const float* b_bnc  = (const float*)d_in[11];
    const float* w1     = (const float*)d_in[12];
    const float* b1     = (const float*)d_in[13];
    const float* g1     = (const float*)d_in[14];
    const float* be1    = (const float*)d_in[15];
    const float* w2     = (const float*)d_in[16];
    const float* b2     = (const float*)d_in[17];
    const float* g2     = (const float*)d_in[18];
    const float* be2    = (const float*)d_in[19];
    const float* w3     = (const float*)d_in[20];
    const float* b3     = (const float*)d_in[21];
    const float* g3     = (const float*)d_in[22];
    const float* be3    = (const float*)d_in[23];
    const float* wout   = (const float*)d_in[24];
    const float* bout   = (const float*)d_in[25];

    int N = in_sizes[0] / 8;
    int E = in_sizes[2] / 8;
    if (N > NMAX) N = NMAX;
    if (E > EMAX) E = EMAX;

    const int fusedSmem = ZDIM * 32 * 8 + 64 * ZDIM * 4;     // 69632 B
    const int postSmem  = 64 * 256 * (int)sizeof(float);     // 65536 B
    cudaFuncSetAttribute(k_fused, cudaFuncAttributeMaxDynamicSharedMemorySize, fusedSmem);
    cudaFuncSetAttribute(k_post,  cudaFuncAttributeMaxDynamicSharedMemorySize, postSmem);

    k_prepA<<<PREP_B, PREP_T>>>(ei, batch, x, N, E);
    k_prepB<<<PREP_B, PREP_T>>>(ei, ea, w_e1, b_e1, E);
    k_fused<<<(N + 63) / 64, 256, fusedSmem>>>(x, w_e2, b_e2, root, cbias, N);
    k_post<<<GRAPHS, 1024, postSmem>>>(g_bnc, b_bnc, w1, b1, g1, be1,
                                       w2, b2, g2, be2, w3, b3, g3, be3,
                                       wout, bout, (float*)d_out, N);
}